// round 1
// baseline (speedup 1.0000x reference)
#include <cuda_runtime.h>
#include <cuda_bf16.h>
#include <cstdint>

// Problem constants
#define B_  16
#define K_  29
#define KP  32           // K padded to 32 (pad lanes hold 0)
#define C_  512
#define S_  16384        // 128*128
#define SPLIT 16         // s-split for kernel 2
#define CHUNK (S_ / SPLIT)   // 1024 s per block
#define TILE 128             // s staged per shared tile

// Scratch: transposed, padded, *normalized* attention: [B][S][KP]  (32 MB)
__device__ float g_attn_t[(size_t)B_ * S_ * KP];
// Per (b,k): {row max, 1/sum}
__device__ float2 g_stats[B_ * KP];

// ---------------- packed f32x2 helpers ----------------
__device__ __forceinline__ void fma2(unsigned long long& acc,
                                     unsigned long long a,
                                     unsigned long long b) {
    asm("fma.rn.f32x2 %0, %1, %2, %0;" : "+l"(acc) : "l"(a), "l"(b));
}
__device__ __forceinline__ unsigned long long pack2(float f) {
    unsigned long long d;
    asm("mov.b64 %0, {%1, %1};" : "=l"(d) : "f"(f));
    return d;
}
__device__ __forceinline__ void unpack2(unsigned long long d, float& lo, float& hi) {
    asm("mov.b64 {%0, %1}, %2;" : "=f"(lo), "=f"(hi) : "l"(d));
}

// ---------------- kernel 0: zero the output ----------------
__global__ void k0_zero(float* __restrict__ out, int n) {
    int i = blockIdx.x * blockDim.x + threadIdx.x;
    if (i < n) out[i] = 0.0f;
}

// ---------------- kernel 1a: per-row max and 1/sum(exp) ----------------
__global__ __launch_bounds__(256) void k1a_stats(const float* __restrict__ probs) {
    const int k = blockIdx.x;   // 0..28
    const int b = blockIdx.y;   // 0..15
    const int tid = threadIdx.x;
    const float* row = probs + ((size_t)(b * K_ + k)) * S_;

    __shared__ float red[256];

    // max
    float m = -1e30f;
    for (int i = tid; i < S_; i += 256) m = fmaxf(m, row[i]);
    red[tid] = m;
    __syncthreads();
    for (int off = 128; off > 0; off >>= 1) {
        if (tid < off) red[tid] = fmaxf(red[tid], red[tid + off]);
        __syncthreads();
    }
    m = red[0];
    __syncthreads();

    // sum of exp
    float s = 0.0f;
    for (int i = tid; i < S_; i += 256) s += __expf(row[i] - m);
    red[tid] = s;
    __syncthreads();
    for (int off = 128; off > 0; off >>= 1) {
        if (tid < off) red[tid] += red[tid + off];
        __syncthreads();
    }
    if (tid == 0) g_stats[b * KP + k] = make_float2(m, 1.0f / red[0]);
}

// ---------------- kernel 1b: normalized attn, transposed to [b][s][KP] ----------------
__global__ __launch_bounds__(256) void k1b_attn(const float* __restrict__ probs) {
    const int b = blockIdx.y;
    const int s = blockIdx.x * 256 + threadIdx.x;   // grid.x = 64 -> covers 16384

    __shared__ float sm[K_], si[K_];
    if (threadIdx.x < K_) {
        float2 st = g_stats[b * KP + threadIdx.x];
        sm[threadIdx.x] = st.x;
        si[threadIdx.x] = st.y;
    }
    __syncthreads();

    float v[KP];
#pragma unroll
    for (int k = 0; k < K_; k++) {
        float x = probs[((size_t)(b * K_ + k)) * S_ + s];
        v[k] = __expf(x - sm[k]) * si[k];
    }
    v[29] = 0.0f; v[30] = 0.0f; v[31] = 0.0f;

    float4* dst = (float4*)(g_attn_t + ((size_t)b * S_ + s) * KP);
#pragma unroll
    for (int i = 0; i < 8; i++)
        dst[i] = make_float4(v[4 * i], v[4 * i + 1], v[4 * i + 2], v[4 * i + 3]);
}

// ---------------- kernel 2: out[b,c,k] = sum_s attn[b,s,k] * feats[b,c,s] ----------------
// grid: (SPLIT, C_/128, B_), block: 128 threads, thread owns one c row.
__global__ __launch_bounds__(128) void k2_gemm(const float* __restrict__ feats,
                                               float* __restrict__ out) {
    const int b  = blockIdx.z;
    const int c  = blockIdx.y * 128 + threadIdx.x;
    const int s0 = blockIdx.x * CHUNK;

    const float* frow  = feats + ((size_t)(b * C_ + c)) * S_ + s0;
    const float* abase = g_attn_t + ((size_t)b * S_ + s0) * KP;

    __shared__ __align__(16) float sh[TILE * KP];   // 16 KB: [128 s][32 k]

    unsigned long long acc[16];
#pragma unroll
    for (int i = 0; i < 16; i++) acc[i] = 0ull;     // bit pattern of {0.f,0.f}

    for (int t = 0; t < CHUNK; t += TILE) {
        __syncthreads();  // protect previous tile's reads
        // stage attn tile: 16 KB, fully coalesced
        const float4* src = (const float4*)(abase + (size_t)t * KP);
        float4* dst = (float4*)sh;
#pragma unroll
        for (int i = 0; i < 8; i++)
            dst[threadIdx.x + i * 128] = src[threadIdx.x + i * 128];
        __syncthreads();

#pragma unroll 2
        for (int j = 0; j < TILE; j += 4) {
            float4 f = *(const float4*)(frow + t + j);
            float fv[4] = {f.x, f.y, f.z, f.w};
#pragma unroll
            for (int u = 0; u < 4; u++) {
                unsigned long long ff = pack2(fv[u]);
                const ulonglong2* ar = (const ulonglong2*)(sh + (j + u) * KP);
#pragma unroll
                for (int i = 0; i < 8; i++) {
                    ulonglong2 p = ar[i];          // LDS.128 broadcast (all threads same s)
                    fma2(acc[2 * i],     p.x, ff); // lanes (2k, 2k+1)
                    fma2(acc[2 * i + 1], p.y, ff);
                }
            }
        }
    }

    // epilogue: out layout (B, C, K, 1) -> (b*C + c)*K + k
    float* o = out + ((size_t)(b * C_ + c)) * K_;
#pragma unroll
    for (int i = 0; i < 16; i++) {
        float lo, hi;
        unpack2(acc[i], lo, hi);
        int k = 2 * i;
        if (k < K_)     atomicAdd(o + k, lo);
        if (k + 1 < K_) atomicAdd(o + k + 1, hi);
    }
}

extern "C" void kernel_launch(void* const* d_in, const int* in_sizes, int n_in,
                              void* d_out, int out_size) {
    const float* feats = (const float*)d_in[0];  // (16, 512, 128, 128)
    const float* probs = (const float*)d_in[1];  // (16, 29, 128, 128)
    float* out = (float*)d_out;                  // (16, 512, 29, 1) fp32

    k0_zero<<<(out_size + 1023) / 1024, 1024>>>(out, out_size);
    k1a_stats<<<dim3(K_, B_), 256>>>(probs);
    k1b_attn<<<dim3(S_ / 256, B_), 256>>>(probs);
    k2_gemm<<<dim3(SPLIT, C_ / 128, B_), 128>>>(feats, out);
}